// round 11
// baseline (speedup 1.0000x reference)
#include <cuda_runtime.h>
#include <math.h>
#include <stdint.h>

#define HIDDEN 1024
#define MEM 32
#define KEY 32
#define VAL 32
#define BATCH 2048
#define TLEN 64
#define BT (BATCH*TLEN)   /* 131072 */
#define NWARMUP 4

/* ---------------- proj tiling --------------------------------------------- */
#define BMp 128            /* rows per CTA */
#define BNp 96             /* proj cols (gate handled separately) */
#define BKp 16             /* k per chunk */
#define NCHUNKS (HIDDEN/BKp)   /* 64 */
/* 256 threads: colgrp = tid&31 (3 cols each), rowgrp = tid>>5 (16 rows each) */

/* ---------------- scratch (static device arrays; no allocation) ----------- */
__device__ float g_Q [BT*KEY];
__device__ float g_FK[BT*KEY];
__device__ float g_FV[BT*VAL];
__device__ float g_G [BT];
/* B weights, scalar, interleaved: [chunk][kk][j*32+colgrp] */
__device__ float g_B[NCHUNKS][BKp][BNp];

/* ---------------- helpers -------------------------------------------------- */
__device__ __forceinline__ void ffma2(unsigned long long& d,
                                      unsigned long long a,
                                      unsigned long long b) {
    asm("fma.rn.f32x2 %0, %1, %2, %0;" : "+l"(d) : "l"(a), "l"(b));
}
__device__ __forceinline__ unsigned long long dup2(float b) {
    unsigned long long r;
    unsigned u = __float_as_uint(b);
    asm("mov.b64 %0, {%1, %1};" : "=l"(r) : "r"(u));
    return r;
}
__device__ __forceinline__ float f2lo(unsigned long long v) {
    return __uint_as_float((unsigned)(v & 0xffffffffu));
}
__device__ __forceinline__ float f2hi(unsigned long long v) {
    return __uint_as_float((unsigned)(v >> 32));
}
__device__ __forceinline__ unsigned redux_umax(unsigned v) {
    unsigned r;
    asm("redux.sync.max.u32 %0, %1, 0xffffffff;" : "=r"(r) : "r"(v));
    return r;
}
__device__ __forceinline__ unsigned redux_umin(unsigned v) {
    unsigned r;
    asm("redux.sync.min.u32 %0, %1, 0xffffffff;" : "=r"(r) : "r"(v));
    return r;
}

/* ---------------- prep: interleave weights (j*32+colgrp layout) ------------ */
__global__ __launch_bounds__(256) void prep_kernel(
    const float* __restrict__ Wq, const float* __restrict__ Wk,
    const float* __restrict__ Wv)
{
    int idx = blockIdx.x * 256 + threadIdx.x;    /* 64*16*96 = 98304 */
    int c   = idx / (BKp * BNp);
    int rem = idx % (BKp * BNp);
    int kk  = rem / BNp;
    int col = rem % BNp;
    int k   = c * BKp + kk;

    float b;
    if      (col < 32) b = Wq[col * HIDDEN + k];
    else if (col < 64) b = Wk[(col - 32) * HIDDEN + k];
    else               b = Wv[(col - 64) * HIDDEN + k];

    int colgrp = col / 3;
    int j      = col % 3;
    g_B[c][kk][j * 32 + colgrp] = b;
}

/* ---------------- dummy: shifts ncu's captured launch (abs idx 3) to proj -- */
__global__ void dummy_kernel(int x) { if (x == 12345) g_G[0] = 0.f; }

/* ---------------- proj kernel: FFMA2 GEMM, broadcast-A tiling -------------- */
__global__ __launch_bounds__(256) void proj_kernel(
    const float* __restrict__ hmat,
    const float* __restrict__ Wg, const float* __restrict__ bg,
    const float* __restrict__ bq, const float* __restrict__ bk_,
    const float* __restrict__ bv)
{
    __shared__ __align__(16) float As[2][BKp][BMp + 4];  /* stride 132: 16B rows */
    __shared__ float Bs[2][BKp][BNp];                    /* scalar, interleaved */
    __shared__ float Gs[2][BKp];

    const int tid    = threadIdx.x;
    const int colgrp = tid & 31;
    const int rowgrp = tid >> 5;            /* warp id: all lanes same rows */
    const long r0    = (long)blockIdx.x * BMp;

    unsigned long long acc[8][3];
    #pragma unroll
    for (int i = 0; i < 8; i++)
        #pragma unroll
        for (int j = 0; j < 3; j++) acc[i][j] = 0ull;
    float accg = 0.f;

    /* prologue: load chunk 0 into regs */
    float4 av[2];        /* A: 2048 floats / 256 thr = 2 float4 */
    float2 bvv[3];       /* B: 1536 floats / 256 thr = 3 float2 */
    float  gv;
    {
        #pragma unroll
        for (int q = 0; q < 2; q++) {
            int i   = tid + 256 * q;      /* 0..511 */
            int row = i >> 2;
            int kg  = (i & 3) * 4;
            av[q] = *(const float4*)(hmat + (r0 + row) * HIDDEN + kg);
        }
        const float2* bsrc = (const float2*)&g_B[0][0][0];
        #pragma unroll
        for (int q = 0; q < 3; q++) bvv[q] = bsrc[tid + 256 * q];
        gv = (tid < BKp) ? Wg[tid] : 0.f;
    }
    /* STS chunk 0 -> stage 0 */
    {
        #pragma unroll
        for (int q = 0; q < 2; q++) {
            int i   = tid + 256 * q;
            int row = i >> 2;
            int kg  = (i & 3) * 4;
            As[0][kg+0][row] = av[q].x;
            As[0][kg+1][row] = av[q].y;
            As[0][kg+2][row] = av[q].z;
            As[0][kg+3][row] = av[q].w;
        }
        float2* bdst = (float2*)&Bs[0][0][0];
        #pragma unroll
        for (int q = 0; q < 3; q++) bdst[tid + 256 * q] = bvv[q];
        if (tid < BKp) Gs[0][tid] = gv;
    }
    __syncthreads();

    for (int c = 0; c < NCHUNKS; c++) {
        const int s = c & 1;

        /* prefetch chunk c+1 into regs */
        if (c + 1 < NCHUNKS) {
            const int k0n = (c + 1) * BKp;
            #pragma unroll
            for (int q = 0; q < 2; q++) {
                int i   = tid + 256 * q;
                int row = i >> 2;
                int kg  = (i & 3) * 4;
                av[q] = *(const float4*)(hmat + (r0 + row) * HIDDEN + k0n + kg);
            }
            const float2* bsrc = (const float2*)&g_B[c + 1][0][0];
            #pragma unroll
            for (int q = 0; q < 3; q++) bvv[q] = bsrc[tid + 256 * q];
            gv = (tid < BKp) ? Wg[k0n + tid] : 0.f;
        }

        /* compute 16 kk from stage s */
        #pragma unroll
        for (int kk = 0; kk < BKp; kk++) {
            /* A: 16 rows = 8 u64 pairs, 4x LDS.128, all lanes broadcast */
            ulonglong2 p0 = *(const ulonglong2*)&As[s][kk][rowgrp * 16 + 0];
            ulonglong2 p1 = *(const ulonglong2*)&As[s][kk][rowgrp * 16 + 4];
            ulonglong2 p2 = *(const ulonglong2*)&As[s][kk][rowgrp * 16 + 8];
            ulonglong2 p3 = *(const ulonglong2*)&As[s][kk][rowgrp * 16 + 12];
            unsigned long long a[8] = { p0.x, p0.y, p1.x, p1.y,
                                        p2.x, p2.y, p3.x, p3.y };
            unsigned long long b[3];
            #pragma unroll
            for (int j = 0; j < 3; j++)
                b[j] = dup2(Bs[s][kk][j * 32 + colgrp]);
            #pragma unroll
            for (int i = 0; i < 8; i++)
                #pragma unroll
                for (int j = 0; j < 3; j++)
                    ffma2(acc[i][j], a[i], b[j]);
            if (tid < 128) accg = fmaf(As[s][kk][tid], Gs[s][kk], accg);
        }

        /* store prefetched chunk to other stage */
        if (c + 1 < NCHUNKS) {
            const int sn = s ^ 1;
            #pragma unroll
            for (int q = 0; q < 2; q++) {
                int i   = tid + 256 * q;
                int row = i >> 2;
                int kg  = (i & 3) * 4;
                As[sn][kg+0][row] = av[q].x;
                As[sn][kg+1][row] = av[q].y;
                As[sn][kg+2][row] = av[q].z;
                As[sn][kg+3][row] = av[q].w;
            }
            float2* bdst = (float2*)&Bs[sn][0][0];
            #pragma unroll
            for (int q = 0; q < 3; q++) bdst[tid + 256 * q] = bvv[q];
            if (tid < BKp) Gs[sn][tid] = gv;
        }
        __syncthreads();
    }

    /* epilogue: 3 cols x 16 rows per thread */
    const int C = colgrp * 3;
    float bias[3];
    float* dstp[3];
    int    cc[3];
    #pragma unroll
    for (int j = 0; j < 3; j++) {
        int col = C + j;
        if      (col < 32) { bias[j] = bq [col];      dstp[j] = g_Q;  cc[j] = col;      }
        else if (col < 64) { bias[j] = bk_[col - 32]; dstp[j] = g_FK; cc[j] = col - 32; }
        else               { bias[j] = bv [col - 64]; dstp[j] = g_FV; cc[j] = col - 64; }
    }
    #pragma unroll
    for (int i = 0; i < 8; i++) {
        long row0 = r0 + rowgrp * 16 + 2 * i;
        #pragma unroll
        for (int j = 0; j < 3; j++) {
            dstp[j][row0       * 32 + cc[j]] = f2lo(acc[i][j]) + bias[j];
            dstp[j][(row0 + 1) * 32 + cc[j]] = f2hi(acc[i][j]) + bias[j];
        }
    }
    if (tid < 128) g_G[r0 + tid] = accg + bg[0];
}

/* ---------------- Kernel 2: recurrence, one warp per batch ----------------- */
#define NW 2

__global__ __launch_bounds__(32*NW) void rnn_kernel(float* __restrict__ es,
                                                    float* __restrict__ ps)
{
    __shared__ float Vs [NW][MEM][VAL+1];
    __shared__ float qs [NW][KEY];
    __shared__ float fks[NW][KEY];
    __shared__ float fvs[NW][VAL];
    __shared__ float ats[NW][MEM];

    const int w    = threadIdx.x >> 5;
    const int lane = threadIdx.x & 31;
    const int b    = blockIdx.x * NW + w;
    const unsigned FULL = 0xffffffffu;
    const float scale = 0.17677669529663688f;

    float K[KEY];
    #pragma unroll
    for (int j = 0; j < KEY; j++) { K[j] = 0.f; Vs[w][lane][j] = 0.f; }
    float Tf = 0.f, msk = 0.f;
    __syncwarp();

    const long row0 = (long)b * TLEN;
    float qv  = g_Q [row0*KEY + lane];
    float fkv = g_FK[row0*KEY + lane];
    float fvv = g_FV[row0*VAL + lane];
    float gx  = g_G [row0];

    for (int t = 0; t < TLEN; t++) {
        const long row  = row0 + t;
        const long nrow = (t < TLEN-1) ? row + 1 : row;

        float nq  = g_Q [nrow*KEY + lane];
        float nfk = g_FK[nrow*KEY + lane];
        float nfv = g_FV[nrow*VAL + lane];
        float ngx = g_G [nrow];

        qs [w][lane] = qv;
        fks[w][lane] = fkv;
        fvs[w][lane] = fvv;
        __syncwarp();

        float lg = 0.f;
        #pragma unroll
        for (int j = 0; j < KEY; j++) lg = fmaf(K[j], qs[w][j], lg);
        lg *= scale;
        float lm = fmaf(1.0f - msk, -1e9f, lg);

        unsigned ub  = __float_as_uint(lm);
        unsigned key = ub ^ ((unsigned)((int)ub >> 31) | 0x80000000u);
        unsigned km  = redux_umax(key);
        unsigned mb  = (km & 0x80000000u) ? (km ^ 0x80000000u) : ~km;
        float mx = __uint_as_float(mb);

        float ex = expf(lm - mx);
        float sm = ex;
        #pragma unroll
        for (int off = 16; off; off >>= 1)
            sm += __shfl_xor_sync(FULL, sm, off);
        float attn = ex / sm;
        ats[w][lane] = attn;

        unsigned ab = __float_as_uint(attn);
        unsigned am = redux_umax(ab);
        int amax = __ffs(__ballot_sync(FULL, ab == am)) - 1;
        __syncwarp();

        float r = 0.f;
        #pragma unroll
        for (int m = 0; m < MEM; m++)
            r = fmaf(ats[w][m], Vs[w][m][lane], r);

        unsigned bal = __ballot_sync(FULL, msk != 0.f);
        bool empty = (bal == 0u);
        bool warm  = (t < NWARMUP);
        float p = 1.f / (1.f + expf(-gx));
        float gate = (empty || warm) ? 0.f : p;
        bool wr = empty || warm || (gx < 0.f);

        float om = 1.0f - gate;
        float e  = gate * r + om * fvv;
        es[row*VAL + lane] = e;
        if (lane == 0) ps[row] = p;

        float evv = Tf + msk * 0.001f;
        unsigned eb = __float_as_uint(evv);
        unsigned em = redux_umin(eb);
        int evict = __ffs(__ballot_sync(FULL, eb == em)) - 1;

        if (wr && lane == evict) {
            msk = 1.f;
            #pragma unroll
            for (int j = 0; j < KEY; j++) {
                K[j] = fks[w][j];
                Vs[w][lane][j] = fvs[w][j];
            }
        }
        int bslot = wr ? evict : amax;
        float A = Tf * 0.85f;
        Tf = (lane == bslot) ? (A + (1.0f - A)) : A;
        __syncwarp();

        qv = nq; fkv = nfk; fvv = nfv; gx = ngx;
    }
}

/* ---------------- launch ---------------------------------------------------- */
extern "C" void kernel_launch(void* const* d_in, const int* in_sizes, int n_in,
                              void* d_out, int out_size)
{
    const float* h  = (const float*)d_in[0];
    const float* Wg = (const float*)d_in[1];
    const float* bg = (const float*)d_in[2];
    const float* Wq = (const float*)d_in[3];
    const float* bq = (const float*)d_in[4];
    const float* Wk = (const float*)d_in[5];
    const float* bk = (const float*)d_in[6];
    const float* Wv = (const float*)d_in[7];
    const float* bv = (const float*)d_in[8];

    float* es = (float*)d_out;
    float* ps = es + ((long)out_size - BT);

    /* launch order keeps proj at absolute index 3 for ncu capture */
    prep_kernel<<<(NCHUNKS*BKp*BNp)/256, 256>>>(Wq, Wk, Wv);
    dummy_kernel<<<1, 32>>>(0);
    dummy_kernel<<<1, 32>>>(0);
    proj_kernel<<<BT/BMp, 256>>>(h, Wg, bg, bq, bk, bv);
    rnn_kernel<<<BATCH/NW, 32*NW>>>(es, ps);
}

// round 12
// speedup vs baseline: 1.0813x; 1.0813x over previous
#include <cuda_runtime.h>
#include <math.h>
#include <stdint.h>

#define HIDDEN 1024
#define MEM 32
#define KEY 32
#define VAL 32
#define BATCH 2048
#define TLEN 64
#define BT (BATCH*TLEN)   /* 131072 */
#define NWARMUP 4

/* ---------------- proj tiling --------------------------------------------- */
#define BMp 128            /* rows per CTA */
#define BNp 96             /* proj cols (gate handled separately) */
#define BKp 16             /* k per chunk */
#define NCHUNKS (HIDDEN/BKp)   /* 64 */
/* 256 threads: colgrp = tid&15 (6 cols each), rowgrp = tid>>4 (8 rows each) */

/* ---------------- scratch (static device arrays; no allocation) ----------- */
__device__ float g_Q [BT*KEY];
__device__ float g_FK[BT*KEY];
__device__ float g_FV[BT*VAL];
__device__ float g_P [BT];          /* sigmoid(gate logit), precomputed */
/* B weights, scalar, interleaved: [chunk][kk][j*16+colgrp] */
__device__ float g_B[NCHUNKS][BKp][BNp];

/* ---------------- helpers -------------------------------------------------- */
__device__ __forceinline__ void ffma2(unsigned long long& d,
                                      unsigned long long a,
                                      unsigned long long b) {
    asm("fma.rn.f32x2 %0, %1, %2, %0;" : "+l"(d) : "l"(a), "l"(b));
}
__device__ __forceinline__ unsigned long long dup2(float b) {
    unsigned long long r;
    unsigned u = __float_as_uint(b);
    asm("mov.b64 %0, {%1, %1};" : "=l"(r) : "r"(u));
    return r;
}
__device__ __forceinline__ float f2lo(unsigned long long v) {
    return __uint_as_float((unsigned)(v & 0xffffffffu));
}
__device__ __forceinline__ float f2hi(unsigned long long v) {
    return __uint_as_float((unsigned)(v >> 32));
}
__device__ __forceinline__ unsigned redux_umax(unsigned v) {
    unsigned r;
    asm("redux.sync.max.u32 %0, %1, 0xffffffff;" : "=r"(r) : "r"(v));
    return r;
}
__device__ __forceinline__ unsigned redux_umin(unsigned v) {
    unsigned r;
    asm("redux.sync.min.u32 %0, %1, 0xffffffff;" : "=r"(r) : "r"(v));
    return r;
}

/* ---------------- prep: interleave weights --------------------------------- */
__global__ __launch_bounds__(256) void prep_kernel(
    const float* __restrict__ Wq, const float* __restrict__ Wk,
    const float* __restrict__ Wv)
{
    int idx = blockIdx.x * 256 + threadIdx.x;    /* 64*16*96 = 98304 */
    int c   = idx / (BKp * BNp);
    int rem = idx % (BKp * BNp);
    int kk  = rem / BNp;
    int col = rem % BNp;
    int k   = c * BKp + kk;

    float b;
    if      (col < 32) b = Wq[col * HIDDEN + k];
    else if (col < 64) b = Wk[(col - 32) * HIDDEN + k];
    else               b = Wv[(col - 64) * HIDDEN + k];

    int colgrp = col / 6;
    int j      = col % 6;
    g_B[c][kk][j * 16 + colgrp] = b;
}

/* ---------------- proj kernel: FFMA2 (f32x2) GEMM, 256 threads ------------- */
__global__ __launch_bounds__(256) void proj_kernel(
    const float* __restrict__ hmat,
    const float* __restrict__ Wg, const float* __restrict__ bg,
    const float* __restrict__ bq, const float* __restrict__ bk_,
    const float* __restrict__ bv)
{
    __shared__ float As[2][BKp][BMp + 2];   /* k-major, stride 130 (even) */
    __shared__ float Bs[2][BKp][BNp];       /* scalar, interleaved */
    __shared__ float Gs[2][BKp];

    const int tid    = threadIdx.x;
    const int colgrp = tid & 15;
    const int rowgrp = tid >> 4;            /* 0..15, 8 rows each */
    const long r0    = (long)blockIdx.x * BMp;

    unsigned long long acc[4][6];
    #pragma unroll
    for (int i = 0; i < 4; i++)
        #pragma unroll
        for (int j = 0; j < 6; j++) acc[i][j] = 0ull;
    float accg = 0.f;

    /* prologue: load chunk 0 into regs */
    float4 av[2];        /* A: 2048 floats / 256 thr = 2 float4 */
    float2 bvv[3];       /* B: 1536 floats / 256 thr = 3 float2 */
    float  gv;
    {
        #pragma unroll
        for (int q = 0; q < 2; q++) {
            int i   = tid + 256 * q;      /* 0..511 */
            int row = i >> 2;
            int kg  = (i & 3) * 4;
            av[q] = *(const float4*)(hmat + (r0 + row) * HIDDEN + kg);
        }
        const float2* bsrc = (const float2*)&g_B[0][0][0];
        #pragma unroll
        for (int q = 0; q < 3; q++) bvv[q] = bsrc[tid + 256 * q];
        gv = (tid < BKp) ? Wg[tid] : 0.f;
    }
    /* STS chunk 0 -> stage 0 */
    {
        #pragma unroll
        for (int q = 0; q < 2; q++) {
            int i   = tid + 256 * q;
            int row = i >> 2;
            int kg  = (i & 3) * 4;
            As[0][kg+0][row] = av[q].x;
            As[0][kg+1][row] = av[q].y;
            As[0][kg+2][row] = av[q].z;
            As[0][kg+3][row] = av[q].w;
        }
        float2* bdst = (float2*)&Bs[0][0][0];
        #pragma unroll
        for (int q = 0; q < 3; q++) bdst[tid + 256 * q] = bvv[q];
        if (tid < BKp) Gs[0][tid] = gv;
    }
    __syncthreads();

    for (int c = 0; c < NCHUNKS; c++) {
        const int s = c & 1;

        /* prefetch chunk c+1 into regs */
        if (c + 1 < NCHUNKS) {
            const int k0n = (c + 1) * BKp;
            #pragma unroll
            for (int q = 0; q < 2; q++) {
                int i   = tid + 256 * q;
                int row = i >> 2;
                int kg  = (i & 3) * 4;
                av[q] = *(const float4*)(hmat + (r0 + row) * HIDDEN + k0n + kg);
            }
            const float2* bsrc = (const float2*)&g_B[c + 1][0][0];
            #pragma unroll
            for (int q = 0; q < 3; q++) bvv[q] = bsrc[tid + 256 * q];
            gv = (tid < BKp) ? Wg[k0n + tid] : 0.f;
        }

        /* compute 16 kk from stage s */
        #pragma unroll
        for (int kk = 0; kk < BKp; kk++) {
            unsigned long long a[4], b[6];
            #pragma unroll
            for (int i = 0; i < 4; i++)
                a[i] = *(const unsigned long long*)&As[s][kk][rowgrp * 8 + 2 * i];
            #pragma unroll
            for (int j = 0; j < 6; j++)
                b[j] = dup2(Bs[s][kk][j * 16 + colgrp]);
            #pragma unroll
            for (int i = 0; i < 4; i++)
                #pragma unroll
                for (int j = 0; j < 6; j++)
                    ffma2(acc[i][j], a[i], b[j]);
            if (tid < 128) accg = fmaf(As[s][kk][tid], Gs[s][kk], accg);
        }

        /* store prefetched chunk to other stage */
        if (c + 1 < NCHUNKS) {
            const int sn = s ^ 1;
            #pragma unroll
            for (int q = 0; q < 2; q++) {
                int i   = tid + 256 * q;
                int row = i >> 2;
                int kg  = (i & 3) * 4;
                As[sn][kg+0][row] = av[q].x;
                As[sn][kg+1][row] = av[q].y;
                As[sn][kg+2][row] = av[q].z;
                As[sn][kg+3][row] = av[q].w;
            }
            float2* bdst = (float2*)&Bs[sn][0][0];
            #pragma unroll
            for (int q = 0; q < 3; q++) bdst[tid + 256 * q] = bvv[q];
            if (tid < BKp) Gs[sn][tid] = gv;
        }
        __syncthreads();
    }

    /* epilogue */
    const int C = colgrp * 6;
    float bias[6];
    #pragma unroll
    for (int j = 0; j < 6; j++) {
        int col = C + j;
        bias[j] = (col < 32) ? bq[col] : (col < 64) ? bk_[col - 32] : bv[col - 64];
    }
    #pragma unroll
    for (int i = 0; i < 4; i++) {
        long row0 = r0 + rowgrp * 8 + 2 * i;
        float v0[6], v1[6];
        #pragma unroll
        for (int j = 0; j < 6; j++) {
            v0[j] = f2lo(acc[i][j]) + bias[j];
            v1[j] = f2hi(acc[i][j]) + bias[j];
        }
        #pragma unroll
        for (int jj = 0; jj < 6; jj += 2) {
            int col = C + jj;
            float* dst;
            int cc;
            if      (col < 32) { dst = g_Q;  cc = col; }
            else if (col < 64) { dst = g_FK; cc = col - 32; }
            else               { dst = g_FV; cc = col - 64; }
            *(float2*)(dst + row0 * 32 + cc)       = make_float2(v0[jj], v0[jj+1]);
            *(float2*)(dst + (row0 + 1) * 32 + cc) = make_float2(v1[jj], v1[jj+1]);
        }
    }
    if (tid < 128) {
        float gx = accg + bg[0];
        g_P[r0 + tid] = 1.f / (1.f + expf(-gx));   /* sigmoid hoisted out of rnn */
    }
}

/* ---------------- Kernel 2: recurrence, one warp per batch ----------------- */
#define NW 2

__global__ __launch_bounds__(32*NW) void rnn_kernel(float* __restrict__ es,
                                                    float* __restrict__ ps)
{
    __shared__ float Vs [NW][MEM][VAL+1];
    __shared__ float qs [NW][KEY];
    __shared__ float fks[NW][KEY];
    __shared__ float fvs[NW][VAL];
    __shared__ float ats[NW][MEM];

    const int w    = threadIdx.x >> 5;
    const int lane = threadIdx.x & 31;
    const int b    = blockIdx.x * NW + w;
    const unsigned FULL = 0xffffffffu;
    const float scale = 0.17677669529663688f;

    float K[KEY];
    #pragma unroll
    for (int j = 0; j < KEY; j++) { K[j] = 0.f; Vs[w][lane][j] = 0.f; }
    float Tf = 0.f, msk = 0.f;
    __syncwarp();

    const long row0 = (long)b * TLEN;
    float qv  = g_Q [row0*KEY + lane];
    float fkv = g_FK[row0*KEY + lane];
    float fvv = g_FV[row0*VAL + lane];
    float pv  = g_P [row0];

    for (int t = 0; t < TLEN; t++) {
        const long row  = row0 + t;
        const long nrow = (t < TLEN-1) ? row + 1 : row;

        float nq  = g_Q [nrow*KEY + lane];
        float nfk = g_FK[nrow*KEY + lane];
        float nfv = g_FV[nrow*VAL + lane];
        float npv = g_P [nrow];

        qs [w][lane] = qv;
        fks[w][lane] = fkv;
        fvs[w][lane] = fvv;
        __syncwarp();

        /* logits chain: order-preserving (decision-critical) */
        float lg = 0.f;
        #pragma unroll
        for (int j = 0; j < KEY; j++) lg = fmaf(K[j], qs[w][j], lg);
        lg *= scale;
        float lm = fmaf(1.0f - msk, -1e9f, lg);

        unsigned ub  = __float_as_uint(lm);
        unsigned key = ub ^ ((unsigned)((int)ub >> 31) | 0x80000000u);
        unsigned km  = redux_umax(key);
        unsigned mb  = (km & 0x80000000u) ? (km ^ 0x80000000u) : ~km;
        float mx = __uint_as_float(mb);

        float ex = expf(lm - mx);
        float sm = ex;
        #pragma unroll
        for (int off = 16; off; off >>= 1)
            sm += __shfl_xor_sync(FULL, sm, off);
        float attn = ex / sm;
        ats[w][lane] = attn;

        unsigned ab = __float_as_uint(attn);
        unsigned am = redux_umax(ab);
        int amax = __ffs(__ballot_sync(FULL, ab == am)) - 1;
        __syncwarp();

        /* retrv: 2-way split (feeds only e_t — continuous, no decisions) */
        float r0a = 0.f, r1a = 0.f;
        #pragma unroll
        for (int m = 0; m < 16; m++)
            r0a = fmaf(ats[w][m], Vs[w][m][lane], r0a);
        #pragma unroll
        for (int m = 16; m < 32; m++)
            r1a = fmaf(ats[w][m], Vs[w][m][lane], r1a);
        float r = r0a + r1a;

        unsigned bal = __ballot_sync(FULL, msk != 0.f);
        bool empty = (bal == 0u);
        bool warm  = (t < NWARMUP);
        float p = pv;
        float gate = (empty || warm) ? 0.f : p;
        bool wr = empty || warm || (p < 0.5f);

        float om = 1.0f - gate;
        float e  = gate * r + om * fvv;
        es[row*VAL + lane] = e;
        if (lane == 0) ps[row] = p;

        float evv = Tf + msk * 0.001f;
        unsigned eb = __float_as_uint(evv);
        unsigned em = redux_umin(eb);
        int evict = __ffs(__ballot_sync(FULL, eb == em)) - 1;

        if (wr && lane == evict) {
            msk = 1.f;
            #pragma unroll
            for (int j = 0; j < KEY; j++) {
                K[j] = fks[w][j];
                Vs[w][lane][j] = fvs[w][j];
            }
        }
        int bslot = wr ? evict : amax;
        float A = Tf * 0.85f;
        Tf = (lane == bslot) ? (A + (1.0f - A)) : A;
        __syncwarp();

        qv = nq; fkv = nfk; fvv = nfv; pv = npv;
    }
}

/* ---------------- launch ---------------------------------------------------- */
extern "C" void kernel_launch(void* const* d_in, const int* in_sizes, int n_in,
                              void* d_out, int out_size)
{
    const float* h  = (const float*)d_in[0];
    const float* Wg = (const float*)d_in[1];
    const float* bg = (const float*)d_in[2];
    const float* Wq = (const float*)d_in[3];
    const float* bq = (const float*)d_in[4];
    const float* Wk = (const float*)d_in[5];
    const float* bk = (const float*)d_in[6];
    const float* Wv = (const float*)d_in[7];
    const float* bv = (const float*)d_in[8];

    float* es = (float*)d_out;
    float* ps = es + ((long)out_size - BT);

    prep_kernel<<<(NCHUNKS*BKp*BNp)/256, 256>>>(Wq, Wk, Wv);
    proj_kernel<<<BT/BMp, 256>>>(h, Wg, bg, bq, bk, bv);
    rnn_kernel<<<BATCH/NW, 32*NW>>>(es, ps);
}

// round 13
// speedup vs baseline: 1.1412x; 1.0554x over previous
#include <cuda_runtime.h>
#include <math.h>
#include <stdint.h>

#define HIDDEN 1024
#define MEM 32
#define KEY 32
#define VAL 32
#define BATCH 2048
#define TLEN 64
#define BT (BATCH*TLEN)   /* 131072 */
#define NWARMUP 4

/* ---------------- proj tiling --------------------------------------------- */
#define BMp 128            /* rows per CTA */
#define BNp 96             /* proj cols (gate handled separately) */
#define BKp 16             /* k per chunk (16-variant) */
#define NCHUNKS (HIDDEN/BKp)   /* 64 */
/* 32-variant: K chunk of 32 = two 16-kk sub-blocks, half the syncthreads */
#define NCH32 (HIDDEN/32)      /* 32 */
/* dynamic smem for proj32: As[2][32][130] + Bs[2][32][96] + Gs[2][32] */
#define SMEM32 ((2*32*130 + 2*32*96 + 2*32) * 4)   /* 58368 B */

/* ---------------- scratch (static device arrays; no allocation) ----------- */
__device__ float g_Q [BT*KEY];
__device__ float g_FK[BT*KEY];
__device__ float g_FV[BT*VAL];
__device__ float g_P [BT];          /* sigmoid(gate logit), precomputed */
/* B weights, scalar, interleaved: [chunk16][kk][j*16+colgrp] */
__device__ float g_B[NCHUNKS][BKp][BNp];

/* ---------------- helpers -------------------------------------------------- */
__device__ __forceinline__ void ffma2(unsigned long long& d,
                                      unsigned long long a,
                                      unsigned long long b) {
    asm("fma.rn.f32x2 %0, %1, %2, %0;" : "+l"(d) : "l"(a), "l"(b));
}
__device__ __forceinline__ unsigned long long dup2(float b) {
    unsigned long long r;
    unsigned u = __float_as_uint(b);
    asm("mov.b64 %0, {%1, %1};" : "=l"(r) : "r"(u));
    return r;
}
__device__ __forceinline__ float f2lo(unsigned long long v) {
    return __uint_as_float((unsigned)(v & 0xffffffffu));
}
__device__ __forceinline__ float f2hi(unsigned long long v) {
    return __uint_as_float((unsigned)(v >> 32));
}
__device__ __forceinline__ unsigned redux_umax(unsigned v) {
    unsigned r;
    asm("redux.sync.max.u32 %0, %1, 0xffffffff;" : "=r"(r) : "r"(v));
    return r;
}
__device__ __forceinline__ unsigned redux_umin(unsigned v) {
    unsigned r;
    asm("redux.sync.min.u32 %0, %1, 0xffffffff;" : "=r"(r) : "r"(v));
    return r;
}

/* ---------------- prep: interleave weights --------------------------------- */
__global__ __launch_bounds__(256) void prep_kernel(
    const float* __restrict__ Wq, const float* __restrict__ Wk,
    const float* __restrict__ Wv)
{
    int idx = blockIdx.x * 256 + threadIdx.x;    /* 64*16*96 = 98304 */
    int c   = idx / (BKp * BNp);
    int rem = idx % (BKp * BNp);
    int kk  = rem / BNp;
    int col = rem % BNp;
    int k   = c * BKp + kk;

    float b;
    if      (col < 32) b = Wq[col * HIDDEN + k];
    else if (col < 64) b = Wk[(col - 32) * HIDDEN + k];
    else               b = Wv[(col - 64) * HIDDEN + k];

    int colgrp = col / 6;
    int j      = col % 6;
    g_B[c][kk][j * 16 + colgrp] = b;
}

/* ============ shared inner-kk body (identical math to R12) ================= */
#define KK_BODY(APTR, BPTR, GPTR)                                             \
    do {                                                                      \
        unsigned long long a_[4], b_[6];                                      \
        _Pragma("unroll")                                                     \
        for (int i_ = 0; i_ < 4; i_++)                                        \
            a_[i_] = *(const unsigned long long*)((APTR) + rowgrp * 8 + 2 * i_); \
        _Pragma("unroll")                                                     \
        for (int j_ = 0; j_ < 6; j_++)                                        \
            b_[j_] = dup2((BPTR)[j_ * 16 + colgrp]);                          \
        _Pragma("unroll")                                                     \
        for (int i_ = 0; i_ < 4; i_++)                                        \
            _Pragma("unroll")                                                 \
            for (int j_ = 0; j_ < 6; j_++)                                    \
                ffma2(acc[i_][j_], a_[i_], b_[j_]);                           \
        if (tid < 128) accg = fmaf((APTR)[tid], *(GPTR), accg);               \
    } while (0)

/* ---------------- proj16: R12 kernel, fallback ----------------------------- */
__global__ __launch_bounds__(256) void proj_kernel16(
    const float* __restrict__ hmat,
    const float* __restrict__ Wg, const float* __restrict__ bg,
    const float* __restrict__ bq, const float* __restrict__ bk_,
    const float* __restrict__ bv)
{
    __shared__ float As[2][BKp][BMp + 2];
    __shared__ float Bs[2][BKp][BNp];
    __shared__ float Gs[2][BKp];

    const int tid    = threadIdx.x;
    const int colgrp = tid & 15;
    const int rowgrp = tid >> 4;
    const long r0    = (long)blockIdx.x * BMp;

    unsigned long long acc[4][6];
    #pragma unroll
    for (int i = 0; i < 4; i++)
        #pragma unroll
        for (int j = 0; j < 6; j++) acc[i][j] = 0ull;
    float accg = 0.f;

    float4 av[2];
    float2 bvv[3];
    float  gv;
    {
        #pragma unroll
        for (int q = 0; q < 2; q++) {
            int i   = tid + 256 * q;
            int row = i >> 2;
            int kg  = (i & 3) * 4;
            av[q] = *(const float4*)(hmat + (r0 + row) * HIDDEN + kg);
        }
        const float2* bsrc = (const float2*)&g_B[0][0][0];
        #pragma unroll
        for (int q = 0; q < 3; q++) bvv[q] = bsrc[tid + 256 * q];
        gv = (tid < BKp) ? Wg[tid] : 0.f;
    }
    {
        #pragma unroll
        for (int q = 0; q < 2; q++) {
            int i   = tid + 256 * q;
            int row = i >> 2;
            int kg  = (i & 3) * 4;
            As[0][kg+0][row] = av[q].x;
            As[0][kg+1][row] = av[q].y;
            As[0][kg+2][row] = av[q].z;
            As[0][kg+3][row] = av[q].w;
        }
        float2* bdst = (float2*)&Bs[0][0][0];
        #pragma unroll
        for (int q = 0; q < 3; q++) bdst[tid + 256 * q] = bvv[q];
        if (tid < BKp) Gs[0][tid] = gv;
    }
    __syncthreads();

    for (int c = 0; c < NCHUNKS; c++) {
        const int s = c & 1;
        if (c + 1 < NCHUNKS) {
            const int k0n = (c + 1) * BKp;
            #pragma unroll
            for (int q = 0; q < 2; q++) {
                int i   = tid + 256 * q;
                int row = i >> 2;
                int kg  = (i & 3) * 4;
                av[q] = *(const float4*)(hmat + (r0 + row) * HIDDEN + k0n + kg);
            }
            const float2* bsrc = (const float2*)&g_B[c + 1][0][0];
            #pragma unroll
            for (int q = 0; q < 3; q++) bvv[q] = bsrc[tid + 256 * q];
            gv = (tid < BKp) ? Wg[k0n + tid] : 0.f;
        }

        #pragma unroll
        for (int kk = 0; kk < BKp; kk++)
            KK_BODY(&As[s][kk][0], &Bs[s][kk][0], &Gs[s][kk]);

        if (c + 1 < NCHUNKS) {
            const int sn = s ^ 1;
            #pragma unroll
            for (int q = 0; q < 2; q++) {
                int i   = tid + 256 * q;
                int row = i >> 2;
                int kg  = (i & 3) * 4;
                As[sn][kg+0][row] = av[q].x;
                As[sn][kg+1][row] = av[q].y;
                As[sn][kg+2][row] = av[q].z;
                As[sn][kg+3][row] = av[q].w;
            }
            float2* bdst = (float2*)&Bs[sn][0][0];
            #pragma unroll
            for (int q = 0; q < 3; q++) bdst[tid + 256 * q] = bvv[q];
            if (tid < BKp) Gs[sn][tid] = gv;
        }
        __syncthreads();
    }

    const int C = colgrp * 6;
    float bias[6];
    #pragma unroll
    for (int j = 0; j < 6; j++) {
        int col = C + j;
        bias[j] = (col < 32) ? bq[col] : (col < 64) ? bk_[col - 32] : bv[col - 64];
    }
    #pragma unroll
    for (int i = 0; i < 4; i++) {
        long row0 = r0 + rowgrp * 8 + 2 * i;
        float v0[6], v1[6];
        #pragma unroll
        for (int j = 0; j < 6; j++) {
            v0[j] = f2lo(acc[i][j]) + bias[j];
            v1[j] = f2hi(acc[i][j]) + bias[j];
        }
        #pragma unroll
        for (int jj = 0; jj < 6; jj += 2) {
            int col = C + jj;
            float* dst;
            int cc;
            if      (col < 32) { dst = g_Q;  cc = col; }
            else if (col < 64) { dst = g_FK; cc = col - 32; }
            else               { dst = g_FV; cc = col - 64; }
            *(float2*)(dst + row0 * 32 + cc)       = make_float2(v0[jj], v0[jj+1]);
            *(float2*)(dst + (row0 + 1) * 32 + cc) = make_float2(v1[jj], v1[jj+1]);
        }
    }
    if (tid < 128) {
        float gx = accg + bg[0];
        g_P[r0 + tid] = 1.f / (1.f + expf(-gx));
    }
}

/* ---------------- proj32: K=32 chunks, half the syncthreads ---------------- */
__global__ __launch_bounds__(256) void proj_kernel32(
    const float* __restrict__ hmat,
    const float* __restrict__ Wg, const float* __restrict__ bg,
    const float* __restrict__ bq, const float* __restrict__ bk_,
    const float* __restrict__ bv)
{
    extern __shared__ float dsm[];
    float* AsP = dsm;                       /* [2][32][130] */
    float* BsP = dsm + 2 * 32 * 130;        /* [2][32][96]  */
    float* GsP = BsP + 2 * 32 * 96;         /* [2][32]      */
#define AS32(s,kk) (AsP + ((s) * 32 + (kk)) * 130)
#define BS32(s,kk) (BsP + ((s) * 32 + (kk)) * 96)
#define GS32(s,kk) (GsP + (s) * 32 + (kk))

    const int tid    = threadIdx.x;
    const int colgrp = tid & 15;
    const int rowgrp = tid >> 4;
    const long r0    = (long)blockIdx.x * BMp;

    unsigned long long acc[4][6];
    #pragma unroll
    for (int i = 0; i < 4; i++)
        #pragma unroll
        for (int j = 0; j < 6; j++) acc[i][j] = 0ull;
    float accg = 0.f;

    float4 av[4];        /* A: 4096 floats / 256 thr = 4 float4 */
    float2 bvv[6];       /* B: 3072 floats / 256 thr = 6 float2 */
    float  gv;
    {
        #pragma unroll
        for (int q = 0; q < 4; q++) {
            int i   = tid + 256 * q;      /* 0..1023 */
            int row = i >> 3;
            int kg  = (i & 7) * 4;
            av[q] = *(const float4*)(hmat + (r0 + row) * HIDDEN + kg);
        }
        const float2* bsrc = (const float2*)&g_B[0][0][0];
        #pragma unroll
        for (int q = 0; q < 6; q++) bvv[q] = bsrc[tid + 256 * q];
        gv = (tid < 32) ? Wg[tid] : 0.f;
    }
    {
        #pragma unroll
        for (int q = 0; q < 4; q++) {
            int i   = tid + 256 * q;
            int row = i >> 3;
            int kg  = (i & 7) * 4;
            AS32(0, kg+0)[row] = av[q].x;
            AS32(0, kg+1)[row] = av[q].y;
            AS32(0, kg+2)[row] = av[q].z;
            AS32(0, kg+3)[row] = av[q].w;
        }
        float2* bdst = (float2*)BS32(0, 0);
        #pragma unroll
        for (int q = 0; q < 6; q++) bdst[tid + 256 * q] = bvv[q];
        if (tid < 32) *GS32(0, tid) = gv;
    }
    __syncthreads();

    for (int c = 0; c < NCH32; c++) {
        const int s = c & 1;
        if (c + 1 < NCH32) {
            const int k0n = (c + 1) * 32;
            #pragma unroll
            for (int q = 0; q < 4; q++) {
                int i   = tid + 256 * q;
                int row = i >> 3;
                int kg  = (i & 7) * 4;
                av[q] = *(const float4*)(hmat + (r0 + row) * HIDDEN + k0n + kg);
            }
            const float2* bsrc = (const float2*)&g_B[2 * (c + 1)][0][0];
            #pragma unroll
            for (int q = 0; q < 6; q++) bvv[q] = bsrc[tid + 256 * q];
            gv = (tid < 32) ? Wg[k0n + tid] : 0.f;
        }

        /* two 16-kk sub-blocks: same inner body as proj16 */
        #pragma unroll
        for (int kk = 0; kk < 16; kk++)
            KK_BODY(AS32(s, kk), BS32(s, kk), GS32(s, kk));
        #pragma unroll
        for (int kk = 16; kk < 32; kk++)
            KK_BODY(AS32(s, kk), BS32(s, kk), GS32(s, kk));

        if (c + 1 < NCH32) {
            const int sn = s ^ 1;
            #pragma unroll
            for (int q = 0; q < 4; q++) {
                int i   = tid + 256 * q;
                int row = i >> 3;
                int kg  = (i & 7) * 4;
                AS32(sn, kg+0)[row] = av[q].x;
                AS32(sn, kg+1)[row] = av[q].y;
                AS32(sn, kg+2)[row] = av[q].z;
                AS32(sn, kg+3)[row] = av[q].w;
            }
            float2* bdst = (float2*)BS32(sn, 0);
            #pragma unroll
            for (int q = 0; q < 6; q++) bdst[tid + 256 * q] = bvv[q];
            if (tid < 32) *GS32(sn, tid) = gv;
        }
        __syncthreads();
    }

    const int C = colgrp * 6;
    float bias[6];
    #pragma unroll
    for (int j = 0; j < 6; j++) {
        int col = C + j;
        bias[j] = (col < 32) ? bq[col] : (col < 64) ? bk_[col - 32] : bv[col - 64];
    }
    #pragma unroll
    for (int i = 0; i < 4; i++) {
        long row0 = r0 + rowgrp * 8 + 2 * i;
        float v0[6], v1[6];
        #pragma unroll
        for (int j = 0; j < 6; j++) {
            v0[j] = f2lo(acc[i][j]) + bias[j];
            v1[j] = f2hi(acc[i][j]) + bias[j];
        }
        #pragma unroll
        for (int jj = 0; jj < 6; jj += 2) {
            int col = C + jj;
            float* dst;
            int cc;
            if      (col < 32) { dst = g_Q;  cc = col; }
            else if (col < 64) { dst = g_FK; cc = col - 32; }
            else               { dst = g_FV; cc = col - 64; }
            *(float2*)(dst + row0 * 32 + cc)       = make_float2(v0[jj], v0[jj+1]);
            *(float2*)(dst + (row0 + 1) * 32 + cc) = make_float2(v1[jj], v1[jj+1]);
        }
    }
    if (tid < 128) {
        float gx = accg + bg[0];
        g_P[r0 + tid] = 1.f / (1.f + expf(-gx));
    }
}

/* ---------------- Kernel 2: recurrence (R12 verbatim) ---------------------- */
#define NW 2

__global__ __launch_bounds__(32*NW) void rnn_kernel(float* __restrict__ es,
                                                    float* __restrict__ ps)
{
    __shared__ float Vs [NW][MEM][VAL+1];
    __shared__ float qs [NW][KEY];
    __shared__ float fks[NW][KEY];
    __shared__ float fvs[NW][VAL];
    __shared__ float ats[NW][MEM];

    const int w    = threadIdx.x >> 5;
    const int lane = threadIdx.x & 31;
    const int b    = blockIdx.x * NW + w;
    const unsigned FULL = 0xffffffffu;
    const float scale = 0.17677669529663688f;

    float K[KEY];
    #pragma unroll
    for (int j = 0; j < KEY; j++) { K[j] = 0.f; Vs[w][lane][j] = 0.f; }
    float Tf = 0.f, msk = 0.f;
    __syncwarp();

    const long row0 = (long)b * TLEN;
    float qv  = g_Q [row0*KEY + lane];
    float fkv = g_FK[row0*KEY + lane];
    float fvv = g_FV[row0*VAL + lane];
    float pv  = g_P [row0];

    for (int t = 0; t < TLEN; t++) {
        const long row  = row0 + t;
        const long nrow = (t < TLEN-1) ? row + 1 : row;

        float nq  = g_Q [nrow*KEY + lane];
        float nfk = g_FK[nrow*KEY + lane];
        float nfv = g_FV[nrow*VAL + lane];
        float npv = g_P [nrow];

        qs [w][lane] = qv;
        fks[w][lane] = fkv;
        fvs[w][lane] = fvv;
        __syncwarp();

        float lg = 0.f;
        #pragma unroll
        for (int j = 0; j < KEY; j++) lg = fmaf(K[j], qs[w][j], lg);
        lg *= scale;
        float lm = fmaf(1.0f - msk, -1e9f, lg);

        unsigned ub  = __float_as_uint(lm);
        unsigned key = ub ^ ((unsigned)((int)ub >> 31) | 0x80000000u);
        unsigned km  = redux_umax(key);
        unsigned mb  = (km & 0x80000000u) ? (km ^ 0x80000000u) : ~km;
        float mx = __uint_as_float(mb);

        float ex = expf(lm - mx);
        float sm = ex;
        #pragma unroll
        for (int off = 16; off; off >>= 1)
            sm += __shfl_xor_sync(FULL, sm, off);
        float attn = ex / sm;
        ats[w][lane] = attn;

        unsigned ab = __float_as_uint(attn);
        unsigned am = redux_umax(ab);
        int amax = __ffs(__ballot_sync(FULL, ab == am)) - 1;
        __syncwarp();

        float r0a = 0.f, r1a = 0.f;
        #pragma unroll
        for (int m = 0; m < 16; m++)
            r0a = fmaf(ats[w][m], Vs[w][m][lane], r0a);
        #pragma unroll
        for (int m = 16; m < 32; m++)
            r1a = fmaf(ats[w][m], Vs[w][m][lane], r1a);
        float r = r0a + r1a;

        unsigned bal = __ballot_sync(FULL, msk != 0.f);
        bool empty = (bal == 0u);
        bool warm  = (t < NWARMUP);
        float p = pv;
        float gate = (empty || warm) ? 0.f : p;
        bool wr = empty || warm || (p < 0.5f);

        float om = 1.0f - gate;
        float e  = gate * r + om * fvv;
        es[row*VAL + lane] = e;
        if (lane == 0) ps[row] = p;

        float evv = Tf + msk * 0.001f;
        unsigned eb = __float_as_uint(evv);
        unsigned em = redux_umin(eb);
        int evict = __ffs(__ballot_sync(FULL, eb == em)) - 1;

        if (wr && lane == evict) {
            msk = 1.f;
            #pragma unroll
            for (int j = 0; j < KEY; j++) {
                K[j] = fks[w][j];
                Vs[w][lane][j] = fvs[w][j];
            }
        }
        int bslot = wr ? evict : amax;
        float A = Tf * 0.85f;
        Tf = (lane == bslot) ? (A + (1.0f - A)) : A;
        __syncwarp();

        qv = nq; fkv = nfk; fvv = nfv; pv = npv;
    }
}

/* ---------------- launch ---------------------------------------------------- */
extern "C" void kernel_launch(void* const* d_in, const int* in_sizes, int n_in,
                              void* d_out, int out_size)
{
    const float* h  = (const float*)d_in[0];
    const float* Wg = (const float*)d_in[1];
    const float* bg = (const float*)d_in[2];
    const float* Wq = (const float*)d_in[3];
    const float* bq = (const float*)d_in[4];
    const float* Wk = (const float*)d_in[5];
    const float* bk = (const float*)d_in[6];
    const float* Wv = (const float*)d_in[7];
    const float* bv = (const float*)d_in[8];

    float* es = (float*)d_out;
    float* ps = es + ((long)out_size - BT);

    prep_kernel<<<(NCHUNKS*BKp*BNp)/256, 256>>>(Wq, Wk, Wv);

    /* runtime dispatch: proj32 only if it kept <=128 regs (2 CTAs/SM) */
    cudaFuncAttributes a32;
    bool use32 = (cudaFuncGetAttributes(&a32, proj_kernel32) == cudaSuccess) &&
                 (a32.numRegs <= 128);
    if (use32) {
        cudaFuncSetAttribute(proj_kernel32,
                             cudaFuncAttributeMaxDynamicSharedMemorySize, SMEM32);
        proj_kernel32<<<BT/BMp, 256, SMEM32>>>(h, Wg, bg, bq, bk, bv);
    } else {
        proj_kernel16<<<BT/BMp, 256>>>(h, Wg, bg, bq, bk, bv);
    }

    rnn_kernel<<<BATCH/NW, 32*NW>>>(es, ps);
}